// round 2
// baseline (speedup 1.0000x reference)
#include <cuda_runtime.h>
#include <math.h>

// ---------------------------------------------------------------------------
// KoopmanPhiICNN encode: 64 Adam steps minimizing ICNN energy over z slice.
// fp32 SIMT GEMMs (128x64x16 tiles, smem double-buffered), fused epilogues.
// Per step: fwd0, fwd1, fwd2, fwd3(->d3), bwd2(->d2,g), bwd1, bwd0, bwdin+Adam.
// Constants c_in / c_x (frozen [x|u] contributions) and softplus(Wzs)
// hoisted out of the step loop.
// R2 fix: mm_nn prologue no longer zero-fills Bs (smem write race).
// ---------------------------------------------------------------------------

#define Bsz 4096
#define Hd  832
#define Zd  256
#define BH  (Bsz*Hd)     // 3,407,872
#define HH  (Hd*Hd)      //   692,224
#define BZ  (Bsz*Zd)     // 1,048,576
#define NSTEPS 64

#define BM 128
#define BN 64
#define BK 16
#define NTHR 256

// ---- scratch layout in one big device array (alloc-free rule) ----
#define O_SWZ  0ull
#define O_SWZO (O_SWZ + 3ull*HH)
#define O_C    (O_SWZO + 832ull)
#define O_H    (O_C   + 4ull*BH)
#define O_DA   (O_H   + 3ull*BH)
#define O_DB   (O_DA  + (unsigned long long)BH)
#define O_G    (O_DB  + (unsigned long long)BH)
#define O_M    (O_G   + (unsigned long long)BZ)
#define O_V    (O_M   + (unsigned long long)BZ)
#define TOTALF (O_V   + (unsigned long long)BZ)

__device__ __align__(16) float g_buf[TOTALF];

__device__ __forceinline__ float sp_(float x) {
    // stable softplus: max(x,0) + log1p(exp(-|x|))
    return fmaxf(x, 0.f) + log1pf(expf(-fabsf(x)));
}
__device__ __forceinline__ float sig_(float x) {
    return 1.f / (1.f + expf(-x));
}
// sigmoid(a) given h = softplus(a):  s = 1 - e^{-h}
__device__ __forceinline__ float sig_from_h(float h) {
    return -expm1f(-h);
}

// ---------------------------------------------------------------------------
// GEMM cores. acc[8][4] per thread; block computes 128x64 of C.
// NT: C[m,n] = sum_k A[m,k]*B[n,k]   (both row-major)
// NN: C[m,n] = sum_k A[m,k]*B[k,n]
// ---------------------------------------------------------------------------

__device__ __forceinline__ void mm_compute(float acc[8][4],
    const float As[BK][BM + 4], const float Bs[BK][BN], int tx, int ty)
{
#pragma unroll
    for (int kk = 0; kk < BK; kk++) {
        float4 a0 = *reinterpret_cast<const float4*>(&As[kk][ty * 8]);
        float4 a1 = *reinterpret_cast<const float4*>(&As[kk][ty * 8 + 4]);
        float4 b  = *reinterpret_cast<const float4*>(&Bs[kk][tx * 4]);
        float av[8] = {a0.x, a0.y, a0.z, a0.w, a1.x, a1.y, a1.z, a1.w};
        float bv[4] = {b.x, b.y, b.z, b.w};
#pragma unroll
        for (int i = 0; i < 8; i++)
#pragma unroll
            for (int j = 0; j < 4; j++)
                acc[i][j] = fmaf(av[i], bv[j], acc[i][j]);
    }
}

__device__ __forceinline__ void st_a(float As[BK][BM + 4],
                                     int r, int c, float4 va0, float4 va1)
{
    As[c + 0][r] = va0.x; As[c + 1][r] = va0.y; As[c + 2][r] = va0.z; As[c + 3][r] = va0.w;
    As[c + 0][r + 64] = va1.x; As[c + 1][r + 64] = va1.y; As[c + 2][r + 64] = va1.z; As[c + 3][r + 64] = va1.w;
}

__device__ __forceinline__ void st_nt(float As[BK][BM + 4], float Bs[BK][BN],
                                      int r, int c, float4 va0, float4 va1, float4 vb)
{
    st_a(As, r, c, va0, va1);
    Bs[c + 0][r] = vb.x; Bs[c + 1][r] = vb.y; Bs[c + 2][r] = vb.z; Bs[c + 3][r] = vb.w;
}

// A row-major [M,K] lda; B row-major [N,K] ldb. kt = K/BK tiles.
__device__ __forceinline__ void mm_nt(float acc[8][4],
    const float* __restrict__ A, int lda,
    const float* __restrict__ Bm, int ldb, int kt,
    int m0, int n0, int tid, int tx, int ty,
    float (&As)[2][BK][BM + 4], float (&Bs)[2][BK][BN])
{
    const int r = tid >> 2;
    const int c = (tid & 3) * 4;
    const float* Ap0 = A + (size_t)(m0 + r) * lda + c;
    const float* Ap1 = A + (size_t)(m0 + r + 64) * lda + c;
    const float* Bp  = Bm + (size_t)(n0 + r) * ldb + c;

    float4 va0 = *reinterpret_cast<const float4*>(Ap0);
    float4 va1 = *reinterpret_cast<const float4*>(Ap1);
    float4 vb  = *reinterpret_cast<const float4*>(Bp);
    __syncthreads();                 // previous users of smem done
    st_nt(As[0], Bs[0], r, c, va0, va1, vb);
    __syncthreads();

    for (int t = 0; t < kt; t++) {
        int buf = t & 1;
        if (t + 1 < kt) {
            va0 = *reinterpret_cast<const float4*>(Ap0 + (t + 1) * BK);
            va1 = *reinterpret_cast<const float4*>(Ap1 + (t + 1) * BK);
            vb  = *reinterpret_cast<const float4*>(Bp  + (t + 1) * BK);
        }
        mm_compute(acc, As[buf], Bs[buf], tx, ty);
        if (t + 1 < kt) st_nt(As[buf ^ 1], Bs[buf ^ 1], r, c, va0, va1, vb);
        __syncthreads();
    }
}

// A row-major [M,K] lda; B element (k, n_local) = Bm[k*ldb + n_local]
// (caller pre-offsets Bm to the starting column). kt = K/BK.
__device__ __forceinline__ void mm_nn(float acc[8][4],
    const float* __restrict__ A, int lda,
    const float* __restrict__ Bm, int ldb, int kt,
    int m0, int tid, int tx, int ty,
    float (&As)[2][BK][BM + 4], float (&Bs)[2][BK][BN])
{
    const int r  = tid >> 2;
    const int c  = (tid & 3) * 4;
    const int rb = tid >> 4;          // k row within tile (0..15)
    const int cb = (tid & 15) * 4;    // n col (0..60)
    const float* Ap0 = A + (size_t)(m0 + r) * lda + c;
    const float* Ap1 = A + (size_t)(m0 + r + 64) * lda + c;
    const float* Bp  = Bm + (size_t)rb * ldb + cb;

    float4 va0 = *reinterpret_cast<const float4*>(Ap0);
    float4 va1 = *reinterpret_cast<const float4*>(Ap1);
    float4 vb  = *reinterpret_cast<const float4*>(Bp);
    __syncthreads();
    st_a(As[0], r, c, va0, va1);                      // A only — no Bs zero-fill
    *reinterpret_cast<float4*>(&Bs[0][rb][cb]) = vb;  // each thread owns its slot
    __syncthreads();

    for (int t = 0; t < kt; t++) {
        int buf = t & 1;
        if (t + 1 < kt) {
            va0 = *reinterpret_cast<const float4*>(Ap0 + (t + 1) * BK);
            va1 = *reinterpret_cast<const float4*>(Ap1 + (t + 1) * BK);
            vb  = *reinterpret_cast<const float4*>(Bp + (size_t)(t + 1) * BK * ldb);
        }
        mm_compute(acc, As[buf], Bs[buf], tx, ty);
        if (t + 1 < kt) {
            int nb = buf ^ 1;
            st_a(As[nb], r, c, va0, va1);
            *reinterpret_cast<float4*>(&Bs[nb][rb][cb]) = vb;
        }
        __syncthreads();
    }
}

// ---------------------------------------------------------------------------
// Kernels
// ---------------------------------------------------------------------------

// Precompute: SWz = softplus(Wzs), swz_out = softplus(wz_out); zero z, m, v.
__global__ void kprep(const float* __restrict__ Wzs, const float* __restrict__ wz_out,
                      float* __restrict__ Z)
{
    float* SWZ  = g_buf + O_SWZ;
    float* SWZO = g_buf + O_SWZO;
    float* Mm   = g_buf + O_M;
    float* Vv   = g_buf + O_V;
    const int n = 3 * HH;
    for (int i = blockIdx.x * blockDim.x + threadIdx.x; i < n;
         i += gridDim.x * blockDim.x) {
        SWZ[i] = sp_(Wzs[i]);
        if (i < Hd) SWZO[i] = sp_(wz_out[i]);
        if (i < BZ) { Z[i] = 0.f; Mm[i] = 0.f; Vv[i] = 0.f; }
    }
}

// c[s] = [x|u] @ W_s[:,256:]^T + bias_s   (s=0: W_in/b_in, s=1..3: Wxs/bs)
__global__ void __launch_bounds__(NTHR) kpre(
    const float* __restrict__ x, const float* __restrict__ u,
    const float* __restrict__ W_in, const float* __restrict__ b_in,
    const float* __restrict__ Wxs, const float* __restrict__ bs)
{
    __shared__ float As[2][BK][BM + 4];
    __shared__ float Bs[2][BK][BN];
    const int tid = threadIdx.x, tx = tid & 15, ty = tid >> 4;
    const int m0 = blockIdx.y * BM, n0 = blockIdx.x * BN;
    const int s = blockIdx.z;
    const float* W    = (s == 0) ? W_in : Wxs + (size_t)(s - 1) * HH;
    const float* bias = (s == 0) ? b_in : bs + (size_t)(s - 1) * Hd;
    float* Out = g_buf + O_C + (size_t)s * BH;

    float acc[8][4];
#pragma unroll
    for (int i = 0; i < 8; i++)
#pragma unroll
        for (int j = 0; j < 4; j++) acc[i][j] = 0.f;

    const int r = tid >> 2;
    const int c = (tid & 3) * 4;
    const int kt = 576 / BK;  // 36 tiles over [x(512) | u(64)]
    const float* Bp = W + (size_t)(n0 + r) * Hd + 256 + c;

    // prologue
    float4 va0, va1, vb;
    {
        int k = c;
        va0 = *reinterpret_cast<const float4*>(&x[(size_t)(m0 + r) * 512 + k]);
        va1 = *reinterpret_cast<const float4*>(&x[(size_t)(m0 + r + 64) * 512 + k]);
        vb  = *reinterpret_cast<const float4*>(Bp);
    }
    __syncthreads();
    st_nt(As[0], Bs[0], r, c, va0, va1, vb);
    __syncthreads();

    for (int t = 0; t < kt; t++) {
        int buf = t & 1;
        if (t + 1 < kt) {
            int k = (t + 1) * BK + c;
            if (k < 512) {
                va0 = *reinterpret_cast<const float4*>(&x[(size_t)(m0 + r) * 512 + k]);
                va1 = *reinterpret_cast<const float4*>(&x[(size_t)(m0 + r + 64) * 512 + k]);
            } else {
                va0 = *reinterpret_cast<const float4*>(&u[(size_t)(m0 + r) * 64 + (k - 512)]);
                va1 = *reinterpret_cast<const float4*>(&u[(size_t)(m0 + r + 64) * 64 + (k - 512)]);
            }
            vb = *reinterpret_cast<const float4*>(Bp + (t + 1) * BK);
        }
        mm_compute(acc, As[buf], Bs[buf], tx, ty);
        if (t + 1 < kt) st_nt(As[buf ^ 1], Bs[buf ^ 1], r, c, va0, va1, vb);
        __syncthreads();
    }

    const float4 b4 = *reinterpret_cast<const float4*>(&bias[n0 + tx * 4]);
#pragma unroll
    for (int i = 0; i < 8; i++) {
        int m = m0 + ty * 8 + i;
        float4 o;
        o.x = acc[i][0] + b4.x; o.y = acc[i][1] + b4.y;
        o.z = acc[i][2] + b4.z; o.w = acc[i][3] + b4.w;
        *reinterpret_cast<float4*>(&Out[(size_t)m * Hd + n0 + tx * 4]) = o;
    }
}

// Forward layer. MODE 0: input layer (h0 = sp(z@Win_z^T + c_in))
//               MODE 1: hidden     (h  = sp(hprev@SWz^T + z@Wx_z^T + c))
//               MODE 2: hidden+final (emit d3 = swz_out * sigmoid(a3))
template<int MODE>
__global__ void __launch_bounds__(NTHR) kfwd(
    const float* __restrict__ A1, const float* __restrict__ B1,
    const float* __restrict__ A2, const float* __restrict__ B2,
    const float* __restrict__ C0, float* __restrict__ Out)
{
    __shared__ float As[2][BK][BM + 4];
    __shared__ float Bs[2][BK][BN];
    const int tid = threadIdx.x, tx = tid & 15, ty = tid >> 4;
    const int m0 = blockIdx.y * BM, n0 = blockIdx.x * BN;

    float acc[8][4];
#pragma unroll
    for (int i = 0; i < 8; i++)
#pragma unroll
        for (int j = 0; j < 4; j++) acc[i][j] = 0.f;

    if (MODE == 0) {
        mm_nt(acc, A1, Zd, B1, Hd, Zd / BK, m0, n0, tid, tx, ty, As, Bs);
    } else {
        mm_nt(acc, A1, Hd, B1, Hd, Hd / BK, m0, n0, tid, tx, ty, As, Bs);
        mm_nt(acc, A2, Zd, B2, Hd, Zd / BK, m0, n0, tid, tx, ty, As, Bs);
    }

    const float* SWZO = g_buf + O_SWZO;
    float4 s4;
    if (MODE == 2) s4 = *reinterpret_cast<const float4*>(&SWZO[n0 + tx * 4]);
#pragma unroll
    for (int i = 0; i < 8; i++) {
        int m = m0 + ty * 8 + i;
        const float4 c4 = *reinterpret_cast<const float4*>(&C0[(size_t)m * Hd + n0 + tx * 4]);
        float v0 = acc[i][0] + c4.x, v1 = acc[i][1] + c4.y;
        float v2 = acc[i][2] + c4.z, v3 = acc[i][3] + c4.w;
        float4 o;
        if (MODE == 2) {
            o.x = s4.x * sig_(v0); o.y = s4.y * sig_(v1);
            o.z = s4.z * sig_(v2); o.w = s4.w * sig_(v3);
        } else {
            o.x = sp_(v0); o.y = sp_(v1); o.z = sp_(v2); o.w = sp_(v3);
        }
        *reinterpret_cast<float4*>(&Out[(size_t)m * Hd + n0 + tx * 4]) = o;
    }
}

// Backward through hidden layer i:
//   n in [0,832):   dnext = (dcur @ SWz_i) * sigma(h_prev)
//   n in [832,1088): g (+)= dcur @ Wx_i[:, :256]     (FIRSTG: g = wx_out + ...)
template<bool FIRSTG>
__global__ void __launch_bounds__(NTHR) kbwd(
    const float* __restrict__ Dcur, const float* __restrict__ SWzL,
    const float* __restrict__ WxL, const float* __restrict__ Hprev,
    float* __restrict__ Dnext, const float* __restrict__ wx_out)
{
    __shared__ float As[2][BK][BM + 4];
    __shared__ float Bs[2][BK][BN];
    const int tid = threadIdx.x, tx = tid & 15, ty = tid >> 4;
    const int m0 = blockIdx.y * BM, n0 = blockIdx.x * BN;
    const bool gpath = (n0 >= Hd);

    float acc[8][4];
#pragma unroll
    for (int i = 0; i < 8; i++)
#pragma unroll
        for (int j = 0; j < 4; j++) acc[i][j] = 0.f;

    const float* Bm = gpath ? (WxL + (n0 - Hd)) : (SWzL + n0);
    mm_nn(acc, Dcur, Hd, Bm, Hd, Hd / BK, m0, tid, tx, ty, As, Bs);

    if (!gpath) {
#pragma unroll
        for (int i = 0; i < 8; i++) {
            int m = m0 + ty * 8 + i;
            const float4 h4 = *reinterpret_cast<const float4*>(&Hprev[(size_t)m * Hd + n0 + tx * 4]);
            float4 o;
            o.x = acc[i][0] * sig_from_h(h4.x);
            o.y = acc[i][1] * sig_from_h(h4.y);
            o.z = acc[i][2] * sig_from_h(h4.z);
            o.w = acc[i][3] * sig_from_h(h4.w);
            *reinterpret_cast<float4*>(&Dnext[(size_t)m * Hd + n0 + tx * 4]) = o;
        }
    } else {
        float* G = g_buf + O_G;
        const int col0 = (n0 - Hd) + tx * 4;
        float4 w4;
        if (FIRSTG) w4 = *reinterpret_cast<const float4*>(&wx_out[col0]);
#pragma unroll
        for (int i = 0; i < 8; i++) {
            int m = m0 + ty * 8 + i;
            size_t idx = (size_t)m * Zd + col0;
            float4 base = FIRSTG ? w4 : *reinterpret_cast<const float4*>(&G[idx]);
            float4 o;
            o.x = base.x + acc[i][0]; o.y = base.y + acc[i][1];
            o.z = base.z + acc[i][2]; o.w = base.w + acc[i][3];
            *reinterpret_cast<float4*>(&G[idx]) = o;
        }
    }
}

// Final backward: g += d0 @ W_in[:, :256], then fused Adam update of z.
__global__ void __launch_bounds__(NTHR) kbwdin(
    const float* __restrict__ Dcur, const float* __restrict__ W_in,
    float* __restrict__ Z, float bc1, float bc2)
{
    __shared__ float As[2][BK][BM + 4];
    __shared__ float Bs[2][BK][BN];
    const int tid = threadIdx.x, tx = tid & 15, ty = tid >> 4;
    const int m0 = blockIdx.y * BM, n0 = blockIdx.x * BN;

    float acc[8][4];
#pragma unroll
    for (int i = 0; i < 8; i++)
#pragma unroll
        for (int j = 0; j < 4; j++) acc[i][j] = 0.f;

    mm_nn(acc, Dcur, Hd, W_in + n0, Hd, Hd / BK, m0, tid, tx, ty, As, Bs);

    const float* G = g_buf + O_G;
    float* Mm = g_buf + O_M;
    float* Vv = g_buf + O_V;
    const int col0 = n0 + tx * 4;
#pragma unroll
    for (int i = 0; i < 8; i++) {
        int m = m0 + ty * 8 + i;
        size_t idx = (size_t)m * Zd + col0;
        float4 g4 = *reinterpret_cast<const float4*>(&G[idx]);
        float gt[4] = {g4.x + acc[i][0], g4.y + acc[i][1],
                       g4.z + acc[i][2], g4.w + acc[i][3]};
        float4 m4 = *reinterpret_cast<const float4*>(&Mm[idx]);
        float4 v4 = *reinterpret_cast<const float4*>(&Vv[idx]);
        float mm[4] = {0.9f * m4.x + 0.1f * gt[0], 0.9f * m4.y + 0.1f * gt[1],
                       0.9f * m4.z + 0.1f * gt[2], 0.9f * m4.w + 0.1f * gt[3]};
        float vv[4] = {0.999f * v4.x + 0.001f * gt[0] * gt[0],
                       0.999f * v4.y + 0.001f * gt[1] * gt[1],
                       0.999f * v4.z + 0.001f * gt[2] * gt[2],
                       0.999f * v4.w + 0.001f * gt[3] * gt[3]};
        *reinterpret_cast<float4*>(&Mm[idx]) = make_float4(mm[0], mm[1], mm[2], mm[3]);
        *reinterpret_cast<float4*>(&Vv[idx]) = make_float4(vv[0], vv[1], vv[2], vv[3]);
        float4 z4 = *reinterpret_cast<float4*>(&Z[idx]);
        z4.x -= 0.01f * (mm[0] * bc1) / (sqrtf(vv[0] * bc2) + 1e-8f);
        z4.y -= 0.01f * (mm[1] * bc1) / (sqrtf(vv[1] * bc2) + 1e-8f);
        z4.z -= 0.01f * (mm[2] * bc1) / (sqrtf(vv[2] * bc2) + 1e-8f);
        z4.w -= 0.01f * (mm[3] * bc1) / (sqrtf(vv[3] * bc2) + 1e-8f);
        *reinterpret_cast<float4*>(&Z[idx]) = z4;
    }
}

// ---------------------------------------------------------------------------
// Host driver (graph-capturable: kernel launches only)
// ---------------------------------------------------------------------------
extern "C" void kernel_launch(void* const* d_in, const int* in_sizes, int n_in,
                              void* d_out, int out_size)
{
    (void)in_sizes; (void)n_in; (void)out_size;
    const float* x      = (const float*)d_in[0];
    const float* u      = (const float*)d_in[1];
    const float* W_in   = (const float*)d_in[2];
    const float* b_in   = (const float*)d_in[3];
    const float* Wzs    = (const float*)d_in[4];
    const float* Wxs    = (const float*)d_in[5];
    const float* bs     = (const float*)d_in[6];
    const float* wz_out = (const float*)d_in[7];
    const float* wx_out = (const float*)d_in[8];
    float* z = (float*)d_out;   // z lives directly in the output buffer

    float* buf = nullptr;
    { void* p = nullptr; cudaGetSymbolAddress(&p, g_buf); buf = (float*)p; }
    float* SWZ = buf + O_SWZ;
    float* C   = buf + O_C;
    float* H0  = buf + O_H;
    float* H1  = buf + O_H + (size_t)BH;
    float* H2  = buf + O_H + 2ull * BH;
    float* DA  = buf + O_DA;
    float* DB  = buf + O_DB;

    dim3 blk(NTHR);

    kprep<<<4096, 512>>>(Wzs, wz_out, z);
    kpre<<<dim3(Hd / BN, Bsz / BM, 4), blk>>>(x, u, W_in, b_in, Wxs, bs);

    const dim3 gF(Hd / BN, Bsz / BM);               // 13 x 32
    const dim3 gB((Hd + Zd) / BN, Bsz / BM);        // 17 x 32
    const dim3 gI(Zd / BN, Bsz / BM);               // 4 x 32

    for (int t = 0; t < NSTEPS; t++) {
        // forward
        kfwd<0><<<gF, blk>>>(z, W_in, nullptr, nullptr, C, H0);
        kfwd<1><<<gF, blk>>>(H0, SWZ,            z, Wxs,             C + 1ull * BH, H1);
        kfwd<1><<<gF, blk>>>(H1, SWZ + 1ull * HH, z, Wxs + 1ull * HH, C + 2ull * BH, H2);
        kfwd<2><<<gF, blk>>>(H2, SWZ + 2ull * HH, z, Wxs + 2ull * HH, C + 3ull * BH, DA); // emits d3
        // backward
        kbwd<true ><<<gB, blk>>>(DA, SWZ + 2ull * HH, Wxs + 2ull * HH, H2, DB, wx_out);
        kbwd<false><<<gB, blk>>>(DB, SWZ + 1ull * HH, Wxs + 1ull * HH, H1, DA, wx_out);
        kbwd<false><<<gB, blk>>>(DA, SWZ,             Wxs,             H0, DB, wx_out);
        double p1 = 1.0, p2 = 1.0;
        for (int q = 0; q <= t; q++) { p1 *= 0.9; p2 *= 0.999; }
        float bc1 = (float)(1.0 / (1.0 - p1));
        float bc2 = (float)(1.0 / (1.0 - p2));
        kbwdin<<<gI, blk>>>(DB, W_in, z, bc1, bc2);
    }
}